// round 13
// baseline (speedup 1.0000x reference)
#include <cuda_runtime.h>
#include <cuda_bf16.h>
#include <math.h>
#include <stdint.h>

// Problem constants (reference: G=2048, CROPS=4, D=128 -> N=8192)
#define N_ROWS 8192
#define DIM    128
#define NP     (N_ROWS / 128)            // 64 row panels

#define EXP2_SCALE 2.8853900817779268f   // 1/(tau*ln2), tau=0.5
#define SQRT_E2S   1.6986436f            // sqrt(EXP2_SCALE), folded into bf16 z
#define EXP_SELF   7.38905609893065f     // exp(1/tau) = e^2

// Scratch (device globals; no allocation anywhere)
__device__ __nv_bfloat16  g_zb[N_ROWS * DIM];       // bf16 normalized * sqrt(scale)
__device__ float          g_P[NP * NP * 128];       // [I][J][row] partial sums
__device__ int            g_cnt[NP];                // per-panel tile completion
__device__ float          g_lpart[NP];              // per-panel loss partials
__device__ int            g_sync;                   // final counter (self-resetting)

// ---------------------------------------------------------------------------
// helpers
// ---------------------------------------------------------------------------
static __device__ __forceinline__ uint32_t smem_u32(const void* p) {
    uint32_t a;
    asm("{ .reg .u64 t; cvta.to.shared.u64 t, %1; cvt.u32.u64 %0, t; }"
        : "=r"(a) : "l"(p));
    return a;
}

#define LDSM_X4(r0, r1, r2, r3, addr)                                          \
    asm volatile("ldmatrix.sync.aligned.m8n8.x4.shared.b16 {%0,%1,%2,%3}, [%4];" \
                 : "=r"(r0), "=r"(r1), "=r"(r2), "=r"(r3) : "r"(addr))

#define MMA16816(d, a, b0, b1)                                                 \
    asm volatile("mma.sync.aligned.m16n8k16.row.col.f32.bf16.bf16.f32 "        \
                 "{%0,%1,%2,%3},{%4,%5,%6,%7},{%8,%9},{%0,%1,%2,%3};"          \
                 : "+f"((d)[0]), "+f"((d)[1]), "+f"((d)[2]), "+f"((d)[3])      \
                 : "r"((a)[0]), "r"((a)[1]), "r"((a)[2]), "r"((a)[3]),         \
                   "r"(b0), "r"(b1))

#define CP_ASYNC16(dst, src)                                                   \
    asm volatile("cp.async.cg.shared.global [%0], [%1], 16;"                   \
                 :: "r"(dst), "l"(src) : "memory")
#define CP_COMMIT() asm volatile("cp.async.commit_group;" ::: "memory")
#define CP_WAIT(N)  asm volatile("cp.async.wait_group %0;" :: "n"(N) : "memory")

static __device__ __forceinline__ float ex2_fast(float x) {
    float y;
    asm("ex2.approx.ftz.f32 %0, %1;" : "=f"(y) : "f"(x));
    return y;
}

// Swizzled tile layout (128 rows x 16 chunks of 16B, conflict-free ldmatrix):
// off(r,c) = (c>>3)*16384 + r*128 + ((c&7)^(r&7))*16
static __device__ __forceinline__ uint32_t tile_off(int r, int c) {
    return ((uint32_t)(c >> 3) << 14) + ((uint32_t)r << 7)
         + ((uint32_t)((c & 7) ^ (r & 7)) << 4);
}

// async-copy one 128x128 bf16 panel (rows r0..r0+127) into swizzled smem
static __device__ __forceinline__ void cp_tile(uint32_t dst, int r0, int tid) {
    const char* src = (const char*)g_zb + (size_t)r0 * 256;
    #pragma unroll
    for (int it = 0; it < 8; it++) {
        int idx = tid + it * 256;       // 2048 chunks of 16B
        int r = idx >> 4;
        int c = idx & 15;
        CP_ASYNC16(dst + tile_off(r, c), src + (size_t)r * 256 + c * 16);
    }
}

// ---------------------------------------------------------------------------
// Kernel A: row-normalize, 4 rows per warp (MLP=4); bf16 * sqrt(EXP2_SCALE)
// ---------------------------------------------------------------------------
__global__ void k_normalize(const float* __restrict__ f, int n) {
    int wid  = (blockIdx.x * blockDim.x + threadIdx.x) >> 5;
    int lane = threadIdx.x & 31;
    int r0 = wid * 4;
    if (r0 >= n) return;

    float4 v[4];
    float  ss[4];
    #pragma unroll
    for (int i = 0; i < 4; i++) {
        v[i] = ((const float4*)(f + (size_t)(r0 + i) * DIM))[lane];
        ss[i] = v[i].x * v[i].x + v[i].y * v[i].y
              + v[i].z * v[i].z + v[i].w * v[i].w;
    }
    #pragma unroll
    for (int o = 16; o; o >>= 1) {
        #pragma unroll
        for (int i = 0; i < 4; i++)
            ss[i] += __shfl_xor_sync(0xffffffffu, ss[i], o);
    }
    #pragma unroll
    for (int i = 0; i < 4; i++) {
        float inv = SQRT_E2S / fmaxf(sqrtf(ss[i]), 1e-8f);
        __nv_bfloat162 lo = __floats2bfloat162_rn(v[i].x * inv, v[i].y * inv);
        __nv_bfloat162 hi = __floats2bfloat162_rn(v[i].z * inv, v[i].w * inv);
        uint2 pk;
        pk.x = *(uint32_t*)&lo;
        pk.y = *(uint32_t*)&hi;
        ((uint2*)(g_zb + (size_t)(r0 + i) * DIM))[lane] = pk;
    }
}

// ---------------------------------------------------------------------------
// Kernel B: symmetric-tile HMMA (round-11 body, occ 3) + FUSED per-panel
// rowloss via completion counters + fused deterministic final reduction.
// ---------------------------------------------------------------------------
__global__ void __launch_bounds__(256, 3)
k_scores_fused(float* __restrict__ out, int n) {
    const int I = blockIdx.x;
    const int J = blockIdx.y;
    if (J < I) return;

    extern __shared__ __align__(1024) char smem[];
    __shared__ float red[128][2];      // row sums: [row][warpN]
    __shared__ float colred[128][4];   // col sums: [col][warpM]
    __shared__ float Ssum[128];
    __shared__ float tvals[8];
    __shared__ float smv[64];
    __shared__ int   ownP[2];
    __shared__ int   s_last;

    const uint32_t Abase = smem_u32(smem);
    const uint32_t Bbase = Abase + 32768;

    const int tid   = threadIdx.x;
    const int lane  = tid & 31;
    const int w     = tid >> 5;
    const int warpM = w & 3;
    const int warpN = w >> 2;

    cp_tile(Abase, I * 128, tid);
    cp_tile(Bbase, J * 128, tid);
    CP_COMMIT();
    CP_WAIT(0);
    __syncthreads();

    const int aRow = warpM * 32 + (lane & 15);
    const int aSel = lane >> 4;
    const int bRow = (lane & 7) + ((lane >> 4) & 1) * 8;
    const int bSel = (lane >> 3) & 1;

    float rs[2][2] = {{0.f, 0.f}, {0.f, 0.f}};

    #pragma unroll
    for (int nbb = 0; nbb < 2; nbb++) {       // n-half-block: cols nbb*32..+31
        float acc[2][2][2][4];                 // [mb][nb2loc][sub][q]
        #pragma unroll
        for (int mb = 0; mb < 2; mb++)
            #pragma unroll
            for (int u = 0; u < 2; u++)
                #pragma unroll
                for (int v = 0; v < 2; v++)
                    #pragma unroll
                    for (int q = 0; q < 4; q++) acc[mb][u][v][q] = 0.0f;

        #pragma unroll
        for (int ks = 0; ks < 8; ks++) {
            uint32_t af[2][4];
            #pragma unroll
            for (int mb = 0; mb < 2; mb++)
                LDSM_X4(af[mb][0], af[mb][1], af[mb][2], af[mb][3],
                        Abase + tile_off(aRow + mb * 16, ks * 2 + aSel));
            #pragma unroll
            for (int u = 0; u < 2; u++) {
                uint32_t b0, b1, b2, b3;
                LDSM_X4(b0, b1, b2, b3,
                        Bbase + tile_off(warpN * 64 + (nbb * 2 + u) * 16 + bRow,
                                         ks * 2 + bSel));
                #pragma unroll
                for (int mb = 0; mb < 2; mb++) {
                    MMA16816(acc[mb][u][0], af[mb], b0, b1);
                    MMA16816(acc[mb][u][1], af[mb], b2, b3);
                }
            }
        }

        // Block epilogue: ex2 + row/col partial sums (overlaps next block's MMAs)
        float cs[8];
        #pragma unroll
        for (int k = 0; k < 8; k++) cs[k] = 0.f;

        #pragma unroll
        for (int mb = 0; mb < 2; mb++)
            #pragma unroll
            for (int u = 0; u < 2; u++)
                #pragma unroll
                for (int v = 0; v < 2; v++)
                    #pragma unroll
                    for (int q = 0; q < 4; q++) {
                        float e = ex2_fast(acc[mb][u][v][q]);
                        rs[mb][q >> 1]                += e;
                        cs[(u * 2 + v) * 2 + (q & 1)] += e;
                    }

        #pragma unroll
        for (int k = 0; k < 8; k++) {
            cs[k] += __shfl_xor_sync(0xffffffffu, cs[k], 4);
            cs[k] += __shfl_xor_sync(0xffffffffu, cs[k], 8);
            cs[k] += __shfl_xor_sync(0xffffffffu, cs[k], 16);
        }
        if (lane < 4) {
            #pragma unroll
            for (int k = 0; k < 8; k++) {
                int nb = nbb * 4 + (k >> 1);           // global 8-col group
                colred[warpN * 64 + nb * 8 + lane * 2 + (k & 1)][warpM] = cs[k];
            }
        }
    }

    // row reduce across lane&3 (cols)
    #pragma unroll
    for (int mb = 0; mb < 2; mb++)
        #pragma unroll
        for (int h = 0; h < 2; h++) {
            rs[mb][h] += __shfl_xor_sync(0xffffffffu, rs[mb][h], 1);
            rs[mb][h] += __shfl_xor_sync(0xffffffffu, rs[mb][h], 2);
        }
    if ((lane & 3) == 0) {
        int gq = lane >> 2;
        #pragma unroll
        for (int mb = 0; mb < 2; mb++)
            #pragma unroll
            for (int h = 0; h < 2; h++)
                red[warpM * 32 + mb * 16 + h * 8 + gq][warpN] = rs[mb][h];
    }
    __syncthreads();

    if (tid < 128) {
        float r = red[tid][0] + red[tid][1];
        g_P[((size_t)I * NP + J) * 128 + tid] = r;
        if (I != J) {
            float c = colred[tid][0] + colred[tid][1]
                    + colred[tid][2] + colred[tid][3];
            g_P[((size_t)J * NP + I) * 128 + tid] = c;
        }
    }

    // ---- fused rowloss: per-panel completion counting -------------------
    __threadfence();                    // release g_P writes
    __syncthreads();
    if (tid == 0) {
        ownP[0] = -1; ownP[1] = -1;
        int np_own = 0;
        int o1 = atomicAdd(&g_cnt[I], 1);
        if (o1 == NP - 1) ownP[np_own++] = I;
        if (J != I) {
            int o2 = atomicAdd(&g_cnt[J], 1);
            if (o2 == NP - 1) ownP[np_own++] = J;
        }
    }
    __syncthreads();

    #pragma unroll 1
    for (int s = 0; s < 2; s++) {
        const int P = ownP[s];
        if (P < 0) break;
        if (tid == 0) g_cnt[P] = 0;     // reset for next graph replay
        __threadfence();                // acquire: all 64 tiles' g_P visible

        // S gather: coalesced, fixed order (tid<128 -> row)
        if (tid < 128) {
            const float* p = g_P + (size_t)P * NP * 128 + tid;
            float sv = 0.0f;
            #pragma unroll 8
            for (int j = 0; j < NP; j++) sv += __ldcg(&p[(size_t)j * 128]);
            Ssum[tid] = sv;
        }
        __syncthreads();

        // group grams: warp w handles groups 4w..4w+3 (4 rows each)
        float tv = 0.0f;
        for (int k = 0; k < 4; k++) {
            const int grow = P * 128 + (w * 4 + k) * 4;
            float2 a[4][2];
            #pragma unroll
            for (int i = 0; i < 4; i++) {
                uint2 pk = ((const uint2*)(g_zb + (size_t)(grow + i) * DIM))[lane];
                a[i][0] = __bfloat1622float2(*(const __nv_bfloat162*)&pk.x);
                a[i][1] = __bfloat1622float2(*(const __nv_bfloat162*)&pk.y);
            }
            float d[16];
            #pragma unroll
            for (int i = 0; i < 4; i++)
                #pragma unroll
                for (int j = 0; j < 4; j++)
                    d[i * 4 + j] = a[i][0].x * a[j][0].x + a[i][0].y * a[j][0].y
                                 + a[i][1].x * a[j][1].x + a[i][1].y * a[j][1].y;
            #pragma unroll
            for (int o = 16; o; o >>= 1) {
                #pragma unroll
                for (int q = 0; q < 16; q++)
                    d[q] += __shfl_xor_sync(0xffffffffu, d[q], o);
            }
            if (lane < 4) {
                float Pp = ex2_fast(d[lane * 4 + 0]) + ex2_fast(d[lane * 4 + 1])
                         + ex2_fast(d[lane * 4 + 2]) + ex2_fast(d[lane * 4 + 3]);
                float S = Ssum[(w * 4 + k) * 4 + lane];
                tv += logf(S - Pp) - logf(Pp - EXP_SELF);
            }
        }
        tv += __shfl_xor_sync(0xffffffffu, tv, 1);
        tv += __shfl_xor_sync(0xffffffffu, tv, 2);
        if (lane == 0) tvals[w] = tv;
        __syncthreads();

        if (tid == 0) {
            float acc = 0.0f;
            #pragma unroll
            for (int u = 0; u < 8; u++) acc += tvals[u];
            g_lpart[P] = acc;
            __threadfence();
            int old = atomicAdd(&g_sync, 1);
            s_last = (old == NP - 1);
        }
        __syncthreads();

        if (s_last) {
            if (tid == 0) g_sync = 0;   // reset for next graph replay
            __threadfence();
            if (tid < 64) smv[tid] = __ldcg(&g_lpart[tid]);
            __syncthreads();
            #pragma unroll
            for (int off = 32; off; off >>= 1) {
                if (tid < off) smv[tid] += smv[tid + off];
                __syncthreads();
            }
            if (tid == 0) out[0] = smv[0] / (float)n;
        }
    }
}

// ---------------------------------------------------------------------------
extern "C" void kernel_launch(void* const* d_in, const int* in_sizes, int n_in,
                              void* d_out, int out_size) {
    const float* features = (const float*)d_in[0];
    int n = in_sizes[0] / DIM;   // 8192

    const int SMEM_DYN = 2 * 32768;   // A panel + B panel
    cudaFuncSetAttribute(k_scores_fused,
                         cudaFuncAttributeMaxDynamicSharedMemorySize, SMEM_DYN);

    k_normalize<<<n / 32, 256>>>(features, n);
    dim3 grid_b(NP, NP);
    k_scores_fused<<<grid_b, 256, SMEM_DYN>>>((float*)d_out, n);
}

// round 14
// speedup vs baseline: 1.3725x; 1.3725x over previous
#include <cuda_runtime.h>
#include <cuda_bf16.h>
#include <math.h>
#include <stdint.h>

// Problem constants (reference: G=2048, CROPS=4, D=128 -> N=8192)
#define N_ROWS 8192
#define DIM    128
#define NP     (N_ROWS / 128)            // 64 row panels
#define NTRI   (NP * (NP + 1) / 2)       // 2080 upper-triangle tiles

#define EXP2_SCALE 2.8853900817779268f   // 1/(tau*ln2), tau=0.5
#define SQRT_E2S   1.6986436f            // sqrt(EXP2_SCALE), folded into bf16 z
#define EXP_SELF   7.38905609893065f     // exp(1/tau) = e^2

// Scratch (device globals; no allocation anywhere)
__device__ __nv_bfloat16  g_zb[N_ROWS * DIM];       // bf16 normalized * sqrt(scale)
__device__ float          g_P[NP * NP * 128];       // [I][J][row] partial sums
__device__ float          g_part[N_ROWS / 32];      // per-block partial losses (256)
__device__ int            g_sync;                   // last-CTA counter (self-resetting)

// ---------------------------------------------------------------------------
// helpers
// ---------------------------------------------------------------------------
static __device__ __forceinline__ uint32_t smem_u32(const void* p) {
    uint32_t a;
    asm("{ .reg .u64 t; cvta.to.shared.u64 t, %1; cvt.u32.u64 %0, t; }"
        : "=r"(a) : "l"(p));
    return a;
}

#define LDSM_X4(r0, r1, r2, r3, addr)                                          \
    asm volatile("ldmatrix.sync.aligned.m8n8.x4.shared.b16 {%0,%1,%2,%3}, [%4];" \
                 : "=r"(r0), "=r"(r1), "=r"(r2), "=r"(r3) : "r"(addr))

#define MMA16816(d, a, b0, b1)                                                 \
    asm volatile("mma.sync.aligned.m16n8k16.row.col.f32.bf16.bf16.f32 "        \
                 "{%0,%1,%2,%3},{%4,%5,%6,%7},{%8,%9},{%0,%1,%2,%3};"          \
                 : "+f"((d)[0]), "+f"((d)[1]), "+f"((d)[2]), "+f"((d)[3])      \
                 : "r"((a)[0]), "r"((a)[1]), "r"((a)[2]), "r"((a)[3]),         \
                   "r"(b0), "r"(b1))

#define CP_ASYNC16(dst, src)                                                   \
    asm volatile("cp.async.cg.shared.global [%0], [%1], 16;"                   \
                 :: "r"(dst), "l"(src) : "memory")
#define CP_COMMIT() asm volatile("cp.async.commit_group;" ::: "memory")
#define CP_WAIT(N)  asm volatile("cp.async.wait_group %0;" :: "n"(N) : "memory")

static __device__ __forceinline__ float ex2_fast(float x) {
    float y;
    asm("ex2.approx.ftz.f32 %0, %1;" : "=f"(y) : "f"(x));
    return y;
}

// Swizzled tile layout (128 rows x 16 chunks of 16B, conflict-free ldmatrix):
// off(r,c) = (c>>3)*16384 + r*128 + ((c&7)^(r&7))*16
static __device__ __forceinline__ uint32_t tile_off(int r, int c) {
    return ((uint32_t)(c >> 3) << 14) + ((uint32_t)r << 7)
         + ((uint32_t)((c & 7) ^ (r & 7)) << 4);
}

// async-copy one 128x128 bf16 panel (rows r0..r0+127) into swizzled smem
static __device__ __forceinline__ void cp_tile(uint32_t dst, int r0, int tid) {
    const char* src = (const char*)g_zb + (size_t)r0 * 256;
    #pragma unroll
    for (int it = 0; it < 8; it++) {
        int idx = tid + it * 256;       // 2048 chunks of 16B
        int r = idx >> 4;
        int c = idx & 15;
        CP_ASYNC16(dst + tile_off(r, c), src + (size_t)r * 256 + c * 16);
    }
}

// ---------------------------------------------------------------------------
// Kernel A: row-normalize, 2 rows per warp (more resident warps, MLP=2)
// ---------------------------------------------------------------------------
__global__ void k_normalize(const float* __restrict__ f, int n) {
    int wid  = (blockIdx.x * blockDim.x + threadIdx.x) >> 5;
    int lane = threadIdx.x & 31;
    int r0 = wid * 2;
    if (r0 >= n) return;

    float4 v[2];
    float  ss[2];
    #pragma unroll
    for (int i = 0; i < 2; i++) {
        v[i] = ((const float4*)(f + (size_t)(r0 + i) * DIM))[lane];
        ss[i] = v[i].x * v[i].x + v[i].y * v[i].y
              + v[i].z * v[i].z + v[i].w * v[i].w;
    }
    #pragma unroll
    for (int o = 16; o; o >>= 1) {
        #pragma unroll
        for (int i = 0; i < 2; i++)
            ss[i] += __shfl_xor_sync(0xffffffffu, ss[i], o);
    }
    #pragma unroll
    for (int i = 0; i < 2; i++) {
        float inv = SQRT_E2S / fmaxf(sqrtf(ss[i]), 1e-8f);
        __nv_bfloat162 lo = __floats2bfloat162_rn(v[i].x * inv, v[i].y * inv);
        __nv_bfloat162 hi = __floats2bfloat162_rn(v[i].z * inv, v[i].w * inv);
        uint2 pk;
        pk.x = *(uint32_t*)&lo;
        pk.y = *(uint32_t*)&hi;
        ((uint2*)(g_zb + (size_t)(r0 + i) * DIM))[lane] = pk;
    }
}

// ---------------------------------------------------------------------------
// Kernel B: symmetric-tile HMMA, one 128x128 tile per CTA, occupancy 3.
// Round-11 winning body; 1D triangular grid (no empty CTAs).
// ---------------------------------------------------------------------------
__global__ void __launch_bounds__(256, 3)
k_scores_sym() {
    // map linear bid -> upper-triangle (I, J)
    int bid = blockIdx.x;
    int I;
    {
        float disc = sqrtf((float)(129 * 129 - 8 * bid));
        I = (int)((129.0f - disc) * 0.5f);
        if (I > NP - 1) I = NP - 1;
        if (I < 0) I = 0;
        while (I * NP - (I * (I - 1)) / 2 > bid) I--;
        while ((I + 1) * NP - ((I + 1) * I) / 2 <= bid) I++;
    }
    const int J = I + (bid - (I * NP - (I * (I - 1)) / 2));

    extern __shared__ __align__(1024) char smem[];
    __shared__ float red[128][2];      // row sums: [row][warpN]
    __shared__ float colred[128][4];   // col sums: [col][warpM]

    const uint32_t Abase = smem_u32(smem);
    const uint32_t Bbase = Abase + 32768;

    const int tid   = threadIdx.x;
    const int lane  = tid & 31;
    const int w     = tid >> 5;
    const int warpM = w & 3;
    const int warpN = w >> 2;

    cp_tile(Abase, I * 128, tid);
    cp_tile(Bbase, J * 128, tid);
    CP_COMMIT();
    CP_WAIT(0);
    __syncthreads();

    const int aRow = warpM * 32 + (lane & 15);
    const int aSel = lane >> 4;
    const int bRow = (lane & 7) + ((lane >> 4) & 1) * 8;
    const int bSel = (lane >> 3) & 1;

    float rs[2][2] = {{0.f, 0.f}, {0.f, 0.f}};

    #pragma unroll
    for (int nbb = 0; nbb < 2; nbb++) {       // n-half-block: cols nbb*32..+31
        float acc[2][2][2][4];                 // [mb][nb2loc][sub][q]
        #pragma unroll
        for (int mb = 0; mb < 2; mb++)
            #pragma unroll
            for (int u = 0; u < 2; u++)
                #pragma unroll
                for (int v = 0; v < 2; v++)
                    #pragma unroll
                    for (int q = 0; q < 4; q++) acc[mb][u][v][q] = 0.0f;

        #pragma unroll
        for (int ks = 0; ks < 8; ks++) {
            uint32_t af[2][4];
            #pragma unroll
            for (int mb = 0; mb < 2; mb++)
                LDSM_X4(af[mb][0], af[mb][1], af[mb][2], af[mb][3],
                        Abase + tile_off(aRow + mb * 16, ks * 2 + aSel));
            #pragma unroll
            for (int u = 0; u < 2; u++) {
                uint32_t b0, b1, b2, b3;
                LDSM_X4(b0, b1, b2, b3,
                        Bbase + tile_off(warpN * 64 + (nbb * 2 + u) * 16 + bRow,
                                         ks * 2 + bSel));
                #pragma unroll
                for (int mb = 0; mb < 2; mb++) {
                    MMA16816(acc[mb][u][0], af[mb][ks] + 0 == af[mb][ks] + 0 ? af[mb] : af[mb], b0, b1);
                    MMA16816(acc[mb][u][1], af[mb], b2, b3);
                }
            }
        }

        // Block epilogue: ex2 + row/col partial sums (overlaps next block's MMAs)
        float cs[8];
        #pragma unroll
        for (int k = 0; k < 8; k++) cs[k] = 0.f;

        #pragma unroll
        for (int mb = 0; mb < 2; mb++)
            #pragma unroll
            for (int u = 0; u < 2; u++)
                #pragma unroll
                for (int v = 0; v < 2; v++)
                    #pragma unroll
                    for (int q = 0; q < 4; q++) {
                        float e = ex2_fast(acc[mb][u][v][q]);
                        rs[mb][q >> 1]                += e;
                        cs[(u * 2 + v) * 2 + (q & 1)] += e;
                    }

        // col reduce across lane>>2 (rows); lane<4 then holds col groups
        #pragma unroll
        for (int k = 0; k < 8; k++) {
            cs[k] += __shfl_xor_sync(0xffffffffu, cs[k], 4);
            cs[k] += __shfl_xor_sync(0xffffffffu, cs[k], 8);
            cs[k] += __shfl_xor_sync(0xffffffffu, cs[k], 16);
        }
        if (lane < 4) {
            #pragma unroll
            for (int k = 0; k < 8; k++) {
                int nb = nbb * 4 + (k >> 1);           // global 8-col group
                colred[warpN * 64 + nb * 8 + lane * 2 + (k & 1)][warpM] = cs[k];
            }
        }
    }

    // row reduce across lane&3 (cols)
    #pragma unroll
    for (int mb = 0; mb < 2; mb++)
        #pragma unroll
        for (int h = 0; h < 2; h++) {
            rs[mb][h] += __shfl_xor_sync(0xffffffffu, rs[mb][h], 1);
            rs[mb][h] += __shfl_xor_sync(0xffffffffu, rs[mb][h], 2);
        }
    if ((lane & 3) == 0) {
        int gq = lane >> 2;
        #pragma unroll
        for (int mb = 0; mb < 2; mb++)
            #pragma unroll
            for (int h = 0; h < 2; h++)
                red[warpM * 32 + mb * 16 + h * 8 + gq][warpN] = rs[mb][h];
    }
    __syncthreads();

    if (tid < 128) {
        float r = red[tid][0] + red[tid][1];
        g_P[((size_t)I * NP + J) * 128 + tid] = r;
        if (I != J) {
            float c = colred[tid][0] + colred[tid][1]
                    + colred[tid][2] + colred[tid][3];
            g_P[((size_t)J * NP + I) * 128 + tid] = c;
        }
    }
}

// ---------------------------------------------------------------------------
// Kernel C: 256 blocks x 32 rows. Warp = one crop-group (4 rows): 4x4 gram
// block via 16 interleaved shuffle chains; rows read coalesced from gmem.
// S gathered coalesced. Fused deterministic last-CTA final reduction.
// ---------------------------------------------------------------------------
__global__ void __launch_bounds__(256) k_rowloss(float* __restrict__ out, int n) {
    __shared__ float Sparts[8][32];   // [part][local row]
    __shared__ float tvals[8];
    __shared__ float sm[256];
    __shared__ int   s_last;

    const int tid  = threadIdx.x;
    const int lane = tid & 31;
    const int wrp  = tid >> 5;
    const int b    = blockIdx.x;          // 32-row block
    const int Ip   = b >> 2;              // panel
    const int rbase = (b & 3) * 32;       // row offset within panel

    // S gather: thread (r = tid&31, part = tid>>5) sums 8 slots, coalesced
    {
        int r = tid & 31;
        int part = tid >> 5;
        const float* p = g_P + ((size_t)Ip * NP + part * 8) * 128 + rbase + r;
        float s = 0.0f;
        #pragma unroll
        for (int j = 0; j < 8; j++) s += p[(size_t)j * 128];
        Sparts[part][r] = s;
    }

    // group gram block: warp wrp owns rows b*32 + wrp*4 .. +3 (one group)
    const int grow = b * 32 + wrp * 4;
    float2 a[4][2];
    #pragma unroll
    for (int i = 0; i < 4; i++) {
        uint2 pk = ((const uint2*)(g_zb + (size_t)(grow + i) * DIM))[lane];
        a[i][0] = __bfloat1622float2(*(const __nv_bfloat162*)&pk.x);
        a[i][1] = __bfloat1622float2(*(const __nv_bfloat162*)&pk.y);
    }

    float d[16];
    #pragma unroll
    for (int i = 0; i < 4; i++)
        #pragma unroll
        for (int j = 0; j < 4; j++)
            d[i * 4 + j] = a[i][0].x * a[j][0].x + a[i][0].y * a[j][0].y
                         + a[i][1].x * a[j][1].x + a[i][1].y * a[j][1].y;

    #pragma unroll
    for (int o = 16; o; o >>= 1) {
        #pragma unroll
        for (int k = 0; k < 16; k++)
            d[k] += __shfl_xor_sync(0xffffffffu, d[k], o);
    }

    __syncthreads();   // Sparts ready

    float tv = 0.0f;
    if (lane < 4) {
        // lane i handles row grow+i (zb pre-scaled: d = cos/(tau*ln2))
        float P = ex2_fast(d[lane * 4 + 0]) + ex2_fast(d[lane * 4 + 1])
                + ex2_fast(d[lane * 4 + 2]) + ex2_fast(d[lane * 4 + 3]);
        int rl = wrp * 4 + lane;
        float S = 0.0f;
        #pragma unroll
        for (int part = 0; part < 8; part++) S += Sparts[part][rl];
        float pos = P - EXP_SELF;
        float neg = S - P;
        tv = logf(neg) - logf(pos);
    }
    tv += __shfl_xor_sync(0xffffffffu, tv, 1);
    tv += __shfl_xor_sync(0xffffffffu, tv, 2);
    if (lane == 0) tvals[wrp] = tv;
    __syncthreads();

    if (tid == 0) {
        float acc = 0.0f;
        #pragma unroll
        for (int u = 0; u < 8; u++) acc += tvals[u];
        g_part[b] = acc;
        __threadfence();
        int old = atomicAdd(&g_sync, 1);
        s_last = (old == (int)gridDim.x - 1);
    }
    __syncthreads();

    if (s_last) {
        if (tid == 0) g_sync = 0;   // reset for next graph replay
        __threadfence();
        int m = gridDim.x;
        float s = 0.0f;
        for (int idx = tid; idx < m; idx += 256)
            s += __ldcg(&g_part[idx]);
        sm[tid] = s;
        __syncthreads();
        #pragma unroll
        for (int off = 128; off; off >>= 1) {
            if (tid < off) sm[tid] += sm[tid + off];
            __syncthreads();
        }
        if (tid == 0) out[0] = sm[0] / (float)n;
    }
}

// ---------------------------------------------------------------------------
extern "C" void kernel_launch(void* const* d_in, const int* in_sizes, int n_in,
                              void* d_out, int out_size) {
    const float* features = (const float*)d_in[0];
    int n = in_sizes[0] / DIM;   // 8192

    const int SMEM_DYN = 2 * 32768;   // A panel + B panel
    cudaFuncSetAttribute(k_scores_sym,
                         cudaFuncAttributeMaxDynamicSharedMemorySize, SMEM_DYN);

    k_normalize<<<n / 16, 256>>>(features, n);
    k_scores_sym<<<NTRI, 256, SMEM_DYN>>>();
    k_rowloss<<<n / 32, 256>>>((float*)d_out, n);
}

// round 15
// speedup vs baseline: 1.4583x; 1.0625x over previous
#include <cuda_runtime.h>
#include <cuda_bf16.h>
#include <math.h>
#include <stdint.h>

// Problem constants (reference: G=2048, CROPS=4, D=128 -> N=8192)
#define N_ROWS 8192
#define DIM    128
#define NP     (N_ROWS / 128)            // 64 row panels
#define NTRI   (NP * (NP + 1) / 2)       // 2080 upper-triangle tiles

#define EXP2_SCALE 2.8853900817779268f   // 1/(tau*ln2), tau=0.5
#define SQRT_E2S   1.6986436f            // sqrt(EXP2_SCALE), folded into bf16 z
#define EXP_SELF   7.38905609893065f     // exp(1/tau) = e^2

// Scratch (device globals; no allocation anywhere)
__device__ __nv_bfloat16  g_zb[N_ROWS * DIM];       // bf16 normalized * sqrt(scale)
__device__ float          g_P[NP * NP * 128];       // [I][J][row] partial sums
__device__ float          g_part[N_ROWS / 32];      // per-block partial losses (256)
__device__ int            g_sync;                   // last-CTA counter (self-resetting)

// ---------------------------------------------------------------------------
// helpers
// ---------------------------------------------------------------------------
static __device__ __forceinline__ uint32_t smem_u32(const void* p) {
    uint32_t a;
    asm("{ .reg .u64 t; cvta.to.shared.u64 t, %1; cvt.u32.u64 %0, t; }"
        : "=r"(a) : "l"(p));
    return a;
}

#define LDSM_X4(r0, r1, r2, r3, addr)                                          \
    asm volatile("ldmatrix.sync.aligned.m8n8.x4.shared.b16 {%0,%1,%2,%3}, [%4];" \
                 : "=r"(r0), "=r"(r1), "=r"(r2), "=r"(r3) : "r"(addr))

#define MMA16816(d, a, b0, b1)                                                 \
    asm volatile("mma.sync.aligned.m16n8k16.row.col.f32.bf16.bf16.f32 "        \
                 "{%0,%1,%2,%3},{%4,%5,%6,%7},{%8,%9},{%0,%1,%2,%3};"          \
                 : "+f"((d)[0]), "+f"((d)[1]), "+f"((d)[2]), "+f"((d)[3])      \
                 : "r"((a)[0]), "r"((a)[1]), "r"((a)[2]), "r"((a)[3]),         \
                   "r"(b0), "r"(b1))

#define CP_ASYNC16(dst, src)                                                   \
    asm volatile("cp.async.cg.shared.global [%0], [%1], 16;"                   \
                 :: "r"(dst), "l"(src) : "memory")
#define CP_COMMIT() asm volatile("cp.async.commit_group;" ::: "memory")
#define CP_WAIT(N)  asm volatile("cp.async.wait_group %0;" :: "n"(N) : "memory")

static __device__ __forceinline__ float ex2_fast(float x) {
    float y;
    asm("ex2.approx.ftz.f32 %0, %1;" : "=f"(y) : "f"(x));
    return y;
}

// Swizzled tile layout (128 rows x 16 chunks of 16B, conflict-free ldmatrix):
// off(r,c) = (c>>3)*16384 + r*128 + ((c&7)^(r&7))*16
static __device__ __forceinline__ uint32_t tile_off(int r, int c) {
    return ((uint32_t)(c >> 3) << 14) + ((uint32_t)r << 7)
         + ((uint32_t)((c & 7) ^ (r & 7)) << 4);
}

// async-copy one 128x128 bf16 panel (rows r0..r0+127) into swizzled smem
static __device__ __forceinline__ void cp_tile(uint32_t dst, int r0, int tid) {
    const char* src = (const char*)g_zb + (size_t)r0 * 256;
    #pragma unroll
    for (int it = 0; it < 8; it++) {
        int idx = tid + it * 256;       // 2048 chunks of 16B
        int r = idx >> 4;
        int c = idx & 15;
        CP_ASYNC16(dst + tile_off(r, c), src + (size_t)r * 256 + c * 16);
    }
}

// ---------------------------------------------------------------------------
// Kernel A: row-normalize, 4 rows per warp; triggers PDL early
// ---------------------------------------------------------------------------
__global__ void k_normalize(const float* __restrict__ f, int n) {
    int wid  = (blockIdx.x * blockDim.x + threadIdx.x) >> 5;
    int lane = threadIdx.x & 31;
    int r0 = wid * 4;
    if (r0 < n) {
        float4 v[4];
        float  ss[4];
        #pragma unroll
        for (int i = 0; i < 4; i++) {
            v[i] = ((const float4*)(f + (size_t)(r0 + i) * DIM))[lane];
            ss[i] = v[i].x * v[i].x + v[i].y * v[i].y
                  + v[i].z * v[i].z + v[i].w * v[i].w;
        }
        #pragma unroll
        for (int o = 16; o; o >>= 1) {
            #pragma unroll
            for (int i = 0; i < 4; i++)
                ss[i] += __shfl_xor_sync(0xffffffffu, ss[i], o);
        }
        #pragma unroll
        for (int i = 0; i < 4; i++) {
            float inv = SQRT_E2S / fmaxf(sqrtf(ss[i]), 1e-8f);
            __nv_bfloat162 lo = __floats2bfloat162_rn(v[i].x * inv, v[i].y * inv);
            __nv_bfloat162 hi = __floats2bfloat162_rn(v[i].z * inv, v[i].w * inv);
            uint2 pk;
            pk.x = *(uint32_t*)&lo;
            pk.y = *(uint32_t*)&hi;
            ((uint2*)(g_zb + (size_t)(r0 + i) * DIM))[lane] = pk;
        }
    }
    cudaTriggerProgrammaticLaunchCompletion();
}

// ---------------------------------------------------------------------------
// Kernel B: symmetric-tile HMMA, one 128x128 tile per CTA, occupancy 3.
// Round-11 winning body; 1D triangular grid; PDL-gated on normalize.
// ---------------------------------------------------------------------------
__global__ void __launch_bounds__(256, 3)
k_scores_sym() {
    // map linear bid -> upper-triangle (I, J)
    int bid = blockIdx.x;
    int I;
    {
        float disc = sqrtf((float)(129 * 129 - 8 * bid));
        I = (int)((129.0f - disc) * 0.5f);
        if (I > NP - 1) I = NP - 1;
        if (I < 0) I = 0;
        while (I * NP - (I * (I - 1)) / 2 > bid) I--;
        while ((I + 1) * NP - ((I + 1) * I) / 2 <= bid) I++;
    }
    const int J = I + (bid - (I * NP - (I * (I - 1)) / 2));

    extern __shared__ __align__(1024) char smem[];
    __shared__ float red[128][2];      // row sums: [row][warpN]
    __shared__ float colred[128][4];   // col sums: [col][warpM]

    const uint32_t Abase = smem_u32(smem);
    const uint32_t Bbase = Abase + 32768;

    const int tid   = threadIdx.x;
    const int lane  = tid & 31;
    const int w     = tid >> 5;
    const int warpM = w & 3;
    const int warpN = w >> 2;

    cudaGridDependencySynchronize();   // g_zb ready (PDL)

    cp_tile(Abase, I * 128, tid);
    cp_tile(Bbase, J * 128, tid);
    CP_COMMIT();
    CP_WAIT(0);
    __syncthreads();

    const int aRow = warpM * 32 + (lane & 15);
    const int aSel = lane >> 4;
    const int bRow = (lane & 7) + ((lane >> 4) & 1) * 8;
    const int bSel = (lane >> 3) & 1;

    float rs[2][2] = {{0.f, 0.f}, {0.f, 0.f}};

    #pragma unroll
    for (int nbb = 0; nbb < 2; nbb++) {       // n-half-block: cols nbb*32..+31
        float acc[2][2][2][4];                 // [mb][nb2loc][sub][q]
        #pragma unroll
        for (int mb = 0; mb < 2; mb++)
            #pragma unroll
            for (int u = 0; u < 2; u++)
                #pragma unroll
                for (int v = 0; v < 2; v++)
                    #pragma unroll
                    for (int q = 0; q < 4; q++) acc[mb][u][v][q] = 0.0f;

        #pragma unroll
        for (int ks = 0; ks < 8; ks++) {
            uint32_t af[2][4];
            #pragma unroll
            for (int mb = 0; mb < 2; mb++)
                LDSM_X4(af[mb][0], af[mb][1], af[mb][2], af[mb][3],
                        Abase + tile_off(aRow + mb * 16, ks * 2 + aSel));
            #pragma unroll
            for (int u = 0; u < 2; u++) {
                uint32_t b0, b1, b2, b3;
                LDSM_X4(b0, b1, b2, b3,
                        Bbase + tile_off(warpN * 64 + (nbb * 2 + u) * 16 + bRow,
                                         ks * 2 + bSel));
                #pragma unroll
                for (int mb = 0; mb < 2; mb++) {
                    MMA16816(acc[mb][u][0], af[mb], b0, b1);
                    MMA16816(acc[mb][u][1], af[mb], b2, b3);
                }
            }
        }

        // Block epilogue: ex2 + row/col partial sums (overlaps next block's MMAs)
        float cs[8];
        #pragma unroll
        for (int k = 0; k < 8; k++) cs[k] = 0.f;

        #pragma unroll
        for (int mb = 0; mb < 2; mb++)
            #pragma unroll
            for (int u = 0; u < 2; u++)
                #pragma unroll
                for (int v = 0; v < 2; v++)
                    #pragma unroll
                    for (int q = 0; q < 4; q++) {
                        float e = ex2_fast(acc[mb][u][v][q]);
                        rs[mb][q >> 1]                += e;
                        cs[(u * 2 + v) * 2 + (q & 1)] += e;
                    }

        // col reduce across lane>>2 (rows); lane<4 then holds col groups
        #pragma unroll
        for (int k = 0; k < 8; k++) {
            cs[k] += __shfl_xor_sync(0xffffffffu, cs[k], 4);
            cs[k] += __shfl_xor_sync(0xffffffffu, cs[k], 8);
            cs[k] += __shfl_xor_sync(0xffffffffu, cs[k], 16);
        }
        if (lane < 4) {
            #pragma unroll
            for (int k = 0; k < 8; k++) {
                int nb = nbb * 4 + (k >> 1);           // global 8-col group
                colred[warpN * 64 + nb * 8 + lane * 2 + (k & 1)][warpM] = cs[k];
            }
        }
    }

    // row reduce across lane&3 (cols)
    #pragma unroll
    for (int mb = 0; mb < 2; mb++)
        #pragma unroll
        for (int h = 0; h < 2; h++) {
            rs[mb][h] += __shfl_xor_sync(0xffffffffu, rs[mb][h], 1);
            rs[mb][h] += __shfl_xor_sync(0xffffffffu, rs[mb][h], 2);
        }
    if ((lane & 3) == 0) {
        int gq = lane >> 2;
        #pragma unroll
        for (int mb = 0; mb < 2; mb++)
            #pragma unroll
            for (int h = 0; h < 2; h++)
                red[warpM * 32 + mb * 16 + h * 8 + gq][warpN] = rs[mb][h];
    }
    __syncthreads();

    if (tid < 128) {
        float r = red[tid][0] + red[tid][1];
        g_P[((size_t)I * NP + J) * 128 + tid] = r;
        if (I != J) {
            float c = colred[tid][0] + colred[tid][1]
                    + colred[tid][2] + colred[tid][3];
            g_P[((size_t)J * NP + I) * 128 + tid] = c;
        }
    }
    cudaTriggerProgrammaticLaunchCompletion();
}

// ---------------------------------------------------------------------------
// Kernel C: 256 blocks x 32 rows. Warp = one crop-group (4 rows): 4x4 gram
// block via 16 interleaved shuffle chains; rows read coalesced from gmem.
// S gathered coalesced. Fused deterministic last-CTA final reduction.
// PDL-gated on scores.
// ---------------------------------------------------------------------------
__global__ void __launch_bounds__(256) k_rowloss(float* __restrict__ out, int n) {
    __shared__ float Sparts[8][32];   // [part][local row]
    __shared__ float tvals[8];
    __shared__ float sm[256];
    __shared__ int   s_last;

    const int tid  = threadIdx.x;
    const int lane = tid & 31;
    const int wrp  = tid >> 5;
    const int b    = blockIdx.x;          // 32-row block
    const int Ip   = b >> 2;              // panel
    const int rbase = (b & 3) * 32;       // row offset within panel

    // group gram rows come from g_zb (ready since normalize); load first
    const int grow = b * 32 + wrp * 4;
    float2 a[4][2];
    #pragma unroll
    for (int i = 0; i < 4; i++) {
        uint2 pk = ((const uint2*)(g_zb + (size_t)(grow + i) * DIM))[lane];
        a[i][0] = __bfloat1622float2(*(const __nv_bfloat162*)&pk.x);
        a[i][1] = __bfloat1622float2(*(const __nv_bfloat162*)&pk.y);
    }

    float d[16];
    #pragma unroll
    for (int i = 0; i < 4; i++)
        #pragma unroll
        for (int j = 0; j < 4; j++)
            d[i * 4 + j] = a[i][0].x * a[j][0].x + a[i][0].y * a[j][0].y
                         + a[i][1].x * a[j][1].x + a[i][1].y * a[j][1].y;

    #pragma unroll
    for (int o = 16; o; o >>= 1) {
        #pragma unroll
        for (int k = 0; k < 16; k++)
            d[k] += __shfl_xor_sync(0xffffffffu, d[k], o);
    }

    cudaGridDependencySynchronize();   // g_P ready (PDL)

    // S gather: thread (r = tid&31, part = tid>>5) sums 8 slots, coalesced
    {
        int r = tid & 31;
        int part = tid >> 5;
        const float* p = g_P + ((size_t)Ip * NP + part * 8) * 128 + rbase + r;
        float s = 0.0f;
        #pragma unroll
        for (int j = 0; j < 8; j++) s += p[(size_t)j * 128];
        Sparts[part][r] = s;
    }
    __syncthreads();   // Sparts ready

    float tv = 0.0f;
    if (lane < 4) {
        // lane i handles row grow+i (zb pre-scaled: d = cos/(tau*ln2))
        float P = ex2_fast(d[lane * 4 + 0]) + ex2_fast(d[lane * 4 + 1])
                + ex2_fast(d[lane * 4 + 2]) + ex2_fast(d[lane * 4 + 3]);
        int rl = wrp * 4 + lane;
        float S = 0.0f;
        #pragma unroll
        for (int part = 0; part < 8; part++) S += Sparts[part][rl];
        float pos = P - EXP_SELF;
        float neg = S - P;
        tv = logf(neg) - logf(pos);
    }
    tv += __shfl_xor_sync(0xffffffffu, tv, 1);
    tv += __shfl_xor_sync(0xffffffffu, tv, 2);
    if (lane == 0) tvals[wrp] = tv;
    __syncthreads();

    if (tid == 0) {
        float acc = 0.0f;
        #pragma unroll
        for (int u = 0; u < 8; u++) acc += tvals[u];
        g_part[b] = acc;
        __threadfence();
        int old = atomicAdd(&g_sync, 1);
        s_last = (old == (int)gridDim.x - 1);
    }
    __syncthreads();

    if (s_last) {
        if (tid == 0) g_sync = 0;   // reset for next graph replay
        __threadfence();
        int m = gridDim.x;
        float s = 0.0f;
        for (int idx = tid; idx < m; idx += 256)
            s += __ldcg(&g_part[idx]);
        sm[tid] = s;
        __syncthreads();
        #pragma unroll
        for (int off = 128; off; off >>= 1) {
            if (tid < off) sm[tid] += sm[tid + off];
            __syncthreads();
        }
        if (tid == 0) out[0] = sm[0] / (float)n;
    }
}

// ---------------------------------------------------------------------------
extern "C" void kernel_launch(void* const* d_in, const int* in_sizes, int n_in,
                              void* d_out, int out_size) {
    const float* features = (const float*)d_in[0];
    int n = in_sizes[0] / DIM;   // 8192
    float* out = (float*)d_out;

    const int SMEM_DYN = 2 * 32768;   // A panel + B panel
    cudaFuncSetAttribute(k_scores_sym,
                         cudaFuncAttributeMaxDynamicSharedMemorySize, SMEM_DYN);

    k_normalize<<<n / 32, 256>>>(features, n);

    cudaLaunchAttribute attr[1];
    attr[0].id = cudaLaunchAttributeProgrammaticStreamSerialization;
    attr[0].val.programmaticStreamSerializationAllowed = 1;

    {
        cudaLaunchConfig_t cfg = {};
        cfg.gridDim = dim3(NTRI, 1, 1);
        cfg.blockDim = dim3(256, 1, 1);
        cfg.dynamicSmemBytes = SMEM_DYN;
        cfg.attrs = attr;
        cfg.numAttrs = 1;
        cudaLaunchKernelEx(&cfg, k_scores_sym);
    }
    {
        cudaLaunchConfig_t cfg = {};
        cfg.gridDim = dim3(n / 32, 1, 1);
        cfg.blockDim = dim3(256, 1, 1);
        cfg.dynamicSmemBytes = 0;
        cfg.attrs = attr;
        cfg.numAttrs = 1;
        cudaLaunchKernelEx(&cfg, k_rowloss, out, n);
    }
}